// round 15
// baseline (speedup 1.0000x reference)
#include <cuda_runtime.h>
#include <cstdint>

namespace {
constexpr int NTHREADS = 256;
constexpr int STF    = 34;             // coeff row stride (floats, even; LDS.64 conflict-free)
constexpr int STH    = 17;             // row stride in float2
constexpr int TILE   = 32;
constexpr int RST    = 64;             // radial tile row stride (floats)
constexpr int NCOEF  = 316;            // 32*1 + 24*3 + 20*5 + 16*7
constexpr int NPAIR  = 1174;           // 528 + 300 + 210 + 136
constexpr int NRAD   = 64;
constexpr int NSP    = 4;
constexpr int NFEAT  = NPAIR + NRAD + 1;   // 1239
constexpr int FSPLIT = 2;
constexpr int FHALF  = 620;            // balanced split: 620 + 619 features
constexpr int HSLOTS = 3;
constexpr int SMAX   = 256;
constexpr int NCOLS  = NSP * NFEAT;    // 4956
constexpr int SM_TILE  = NCOEF * STF;              // floats
constexpr int SM_RAD   = TILE * RST;               // floats
constexpr int SM_TOTAL = (SM_TILE + SM_RAD + TILE) * 4;   // 51296 bytes
}

__device__ int g_run[SMAX * 5];        // padded run starts sp=0..3, then padded end
__device__ int g_order[1 << 16];       // atom idx by (structure, species); -1 = pad

__device__ __forceinline__ void cpa4(uint32_t dst, const void* src, int sz) {
    asm volatile("cp.async.ca.shared.global [%0], [%1], 4, %2;"
                 :: "r"(dst), "l"(src), "r"(sz));
}
__device__ __forceinline__ void cpa16(uint32_t dst, const void* src, int sz) {
    asm volatile("cp.async.ca.shared.global [%0], [%1], 16, %2;"
                 :: "r"(dst), "l"(src), "r"(sz));
}
__device__ __forceinline__ void cpa_commit_wait() {
    asm volatile("cp.async.commit_group;" ::: "memory");
    asm volatile("cp.async.wait_group 0;" ::: "memory");
}

// One block per structure. Deterministic species sort (warp-major, lane-minor
// rank) into padded slots: structure s starts at a0 + 4*s; each species run is
// padded to even length with -1 entries (staged as zeros -> no contribution).
__global__ void setup_kernel(const int* __restrict__ sidx,
                             const int* __restrict__ species, int n_atoms) {
    const int s    = blockIdx.x;
    const int tid  = threadIdx.x;
    const int lane = tid & 31;
    const int wid  = tid >> 5;
    __shared__ int cnt[NSP], off[NSP], runb[NSP], wcnt[8][NSP];

    int lo = 0, hi = n_atoms;
    while (lo < hi) { int mid = (lo + hi) >> 1; if (sidx[mid] < s) lo = mid + 1; else hi = mid; }
    const int a0 = lo;
    lo = a0; hi = n_atoms;
    while (lo < hi) { int mid = (lo + hi) >> 1; if (sidx[mid] < s + 1) lo = mid + 1; else hi = mid; }
    const int a1 = lo;

    if (tid < NSP) cnt[tid] = 0;
    __syncthreads();
    for (int chunk = a0; chunk < a1; chunk += NTHREADS) {
        const int n  = min(NTHREADS, a1 - chunk);
        const int sp = (tid < n) ? species[chunk + tid] : -1;
        const unsigned m = __match_any_sync(0xFFFFFFFFu, sp);
        if (sp >= 0 && (m & ((1u << lane) - 1u)) == 0)
            atomicAdd(&cnt[sp], __popc(m));
    }
    __syncthreads();
    if (tid == 0) {
        int p = a0 + 4 * s;                 // padded base (4 reserved pads/structure)
#pragma unroll
        for (int q = 0; q < NSP; ++q) {
            g_run[s * 5 + q] = p; runb[q] = p; off[q] = p;
            p += (cnt[q] + 1) & ~1;         // pad run to even length
        }
        g_run[s * 5 + 4] = p;
    }
    __syncthreads();
    if (tid < NSP && (cnt[tid] & 1)) g_order[runb[tid] + cnt[tid]] = -1;  // pad slot
    for (int chunk = a0; chunk < a1; chunk += NTHREADS) {
        const int n  = min(NTHREADS, a1 - chunk);
        const int sp = (tid < n) ? species[chunk + tid] : -1;
        const unsigned m = __match_any_sync(0xFFFFFFFFu, sp);
        const int rank_w = __popc(m & ((1u << lane) - 1u));
        if (lane < NSP) wcnt[wid][lane] = 0;
        __syncthreads();
        if (sp >= 0 && rank_w == 0) wcnt[wid][sp] = __popc(m);
        __syncthreads();
        if (sp >= 0) {
            int pre = 0;
            for (int w = 0; w < wid; ++w) pre += wcnt[w][sp];
            g_order[off[sp] + pre + rank_w] = chunk + tid;
        }
        __syncthreads();
        if (tid < NSP) {
            int tot = 0;
#pragma unroll
            for (int w = 0; w < 8; ++w) tot += wcnt[w][tid];
            off[tid] += tot;
        }
        __syncthreads();
    }
}

// One float2 step of the pair invariant at half-index h.
template<int D>
__device__ __forceinline__ void pair_step(const float2* __restrict__ b1,
                                          const float2* __restrict__ b2,
                                          int h, float& a0, float& a1) {
#pragma unroll
    for (int j = 0; j < D; ++j) {
        const float2 x = b1[j * STH + h];
        const float2 y = b2[(D - 1 - j) * STH + h];
        if (j & 1) { a0 = fmaf(-x.x, y.x, a0); a1 = fmaf(-x.y, y.y, a1); }
        else       { a0 = fmaf( x.x, y.x, a0); a1 = fmaf( x.y, y.y, a1); }
    }
}

// Pair invariant over [h0,h1) float2-pairs, manual 2x unroll -> 4 FMA chains.
template<int D>
__device__ __forceinline__ float run_pairs2(const float2* __restrict__ b1,
                                            const float2* __restrict__ b2,
                                            int h0, int h1) {
    float ax = 0.f, ay = 0.f, az = 0.f, aw = 0.f;
    int h = h0;
    for (; h + 2 <= h1; h += 2) {
        pair_step<D>(b1, b2, h,     ax, ay);
        pair_step<D>(b1, b2, h + 1, az, aw);
    }
    if (h < h1) pair_step<D>(b1, b2, h, ax, ay);
    return (ax + ay) + (az + aw);
}

__global__ __launch_bounds__(NTHREADS, 4)
void le_ace_kernel(const float* __restrict__ comp,
                   const float* __restrict__ radial,
                   const float* __restrict__ sph0,
                   const float* __restrict__ sph1,
                   const float* __restrict__ sph2,
                   const float* __restrict__ sph3,
                   float* __restrict__ out,
                   int n_atoms) {
    extern __shared__ __align__(16) float smem[];
    float* tileS = smem;                    // [NCOEF * STF]
    float* radT  = smem + SM_TILE;          // [TILE * RST]
    float* compT = radT + SM_RAD;           // [TILE]

    const int tid   = threadIdx.x;
    const int lane  = tid & 31;
    const int wid   = tid >> 5;
    const int s     = blockIdx.x;
    const int split = blockIdx.y;

    const uint32_t sb_tile = (uint32_t)__cvta_generic_to_shared(tileS);
    const uint32_t sb_rad  = (uint32_t)__cvta_generic_to_shared(radT);
    const uint32_t sb_cmp  = (uint32_t)__cvta_generic_to_shared(compT);

    const int fbase0 = split * FHALF;       // split0: [0,620), split1: [620,1239)
    const int fend   = split ? NFEAT : FHALF;

    // ---- per-thread feature-slot metadata ----
    // sdv: 1/3/5/7 = pair D; 0 = radial (sc1 = col); -1 = comp; -2 = inactive
    int   sc1[HSLOTS], sc2[HSLOTS], sdv[HSLOTS];
    float facc[HSLOTS][NSP];
#pragma unroll
    for (int k = 0; k < HSLOTS; ++k) {
        int f = fbase0 + k * NTHREADS + tid;
        sc1[k] = 0; sc2[k] = 0; sdv[k] = -2;
#pragma unroll
        for (int sp = 0; sp < NSP; ++sp) facc[k][sp] = 0.f;
        if (f < fend) {
            if (f < NPAIR) {
                int l, q, base, coff;
                if (f < 528)       { l = 0; q = 32; base = 0;    coff = 0;   }
                else if (f < 828)  { l = 1; q = 24; base = 528;  coff = 32;  }
                else if (f < 1038) { l = 2; q = 20; base = 828;  coff = 104; }
                else               { l = 3; q = 16; base = 1038; coff = 204; }
                int rem = f - base, i1 = 0;
                while (rem >= q - i1) { rem -= q - i1; ++i1; }   // triangular inversion
                int i2 = i1 + rem;
                int d  = 2 * l + 1;
                sc1[k] = (coff + i1 * d) * STH;   // float2 row offsets
                sc2[k] = (coff + i2 * d) * STH;
                sdv[k] = d;
            } else if (f < NPAIR + NRAD) {
                sdv[k] = 0; sc1[k] = f - NPAIR;
            } else {
                sdv[k] = -1;
            }
        }
    }

    int run[5];
#pragma unroll
    for (int r = 0; r < 5; ++r) run[r] = g_run[s * 5 + r];
    const int a0 = run[0];
    const int a1 = run[4];                  // padded end (a1 - a0 even)

    for (int base = a0; base < a1; base += TILE) {
        const int nt = min(TILE, a1 - base);   // even
        __syncthreads();                       // previous tile fully consumed

        // ---- async staging: coeff rows (each thread ~40 x 4B, deep MLP) ----
        const int  oL  = (base + lane < a1) ? g_order[base + lane] : -1;
        const int  oLc = max(oL, 0);
        const int  szL = (oL >= 0) ? 4 : 0;
        for (int c = wid; c < NCOEF; c += 8) {
            const float* p; int r;
            if (c < 32)       { p = sph0; r = c;       }
            else if (c < 104) { p = sph1; r = c - 32;  }
            else if (c < 204) { p = sph2; r = c - 104; }
            else              { p = sph3; r = c - 204; }
            cpa4(sb_tile + ((c * STF + lane) << 2), p + (long)r * n_atoms + oLc, szL);
        }
        // ---- radial tile: 32 atoms x 64 floats, 16B chunks ----
#pragma unroll
        for (int i = 0; i < 2; ++i) {
            const int idx = tid + NTHREADS * i;   // 0..511
            const int ta  = idx >> 4;
            const int ch  = idx & 15;
            const int o   = (base + ta < a1) ? g_order[base + ta] : -1;
            cpa16(sb_rad + (ta * RST + ch * 4) * 4,
                  radial + (long)max(o, 0) * NRAD + ch * 4, (o >= 0) ? 16 : 0);
        }
        // ---- comp tile ----
        if (tid < TILE)
            cpa4(sb_cmp + (tid << 2), comp + oLc, szL);
        cpa_commit_wait();
        __syncthreads();

        // ---- species bounds, hoisted (all even; shared by the 3 slots) ----
        int t0s[NSP], t1s[NSP];
#pragma unroll
        for (int sp = 0; sp < NSP; ++sp) {
            t0s[sp] = max(run[sp] - base, 0);
            t1s[sp] = min(run[sp + 1] - base, nt);
        }

        // ---- accumulate ----
        const float2* T2 = (const float2*)tileS;
#pragma unroll
        for (int k = 0; k < HSLOTS; ++k) {
            const int d = sdv[k];
            if (d > 0) {
                const float2* b1 = T2 + sc1[k];
                const float2* b2 = T2 + sc2[k];
#pragma unroll
                for (int sp = 0; sp < NSP; ++sp) {
                    const int h0 = t0s[sp] >> 1, h1 = t1s[sp] >> 1;
                    if (h0 >= h1) continue;
                    float v;
                    switch (d) {
                        case 1:  v = run_pairs2<1>(b1, b2, h0, h1); break;
                        case 3:  v = run_pairs2<3>(b1, b2, h0, h1); break;
                        case 5:  v = run_pairs2<5>(b1, b2, h0, h1); break;
                        default: v = run_pairs2<7>(b1, b2, h0, h1); break;
                    }
                    facc[k][sp] += v;
                }
            } else if (d == 0) {
                const int j = sc1[k];
#pragma unroll
                for (int sp = 0; sp < NSP; ++sp) {
                    float acc = 0.f;
                    for (int t = t0s[sp]; t < t1s[sp]; ++t)   // pads staged as 0
                        acc += radT[t * RST + j];
                    facc[k][sp] += acc;
                }
            } else if (d == -1) {
#pragma unroll
                for (int sp = 0; sp < NSP; ++sp) {
                    float acc = 0.f;
                    for (int t = t0s[sp]; t < t1s[sp]; ++t)
                        acc += compT[t];
                    facc[k][sp] += acc;
                }
            }
        }
    }

    // ---- write: scale recomputed here (keeps it out of hot-loop registers) ----
#pragma unroll
    for (int k = 0; k < HSLOTS; ++k) {
        int f = fbase0 + k * NTHREADS + tid;
        if (f >= fend) continue;
        float sc = 1.f;
        if (f < NPAIR) {
            int l, q, base;
            if (f < 528)       { l = 0; q = 32; base = 0;    }
            else if (f < 828)  { l = 1; q = 24; base = 528;  }
            else if (f < 1038) { l = 2; q = 20; base = 828;  }
            else               { l = 3; q = 16; base = 1038; }
            int rem = f - base, i1 = 0;
            while (rem >= q - i1) { rem -= q - i1; ++i1; }
            const float invsq[4] = {1.0f, 0.5773502691896258f,
                                    0.4472135954999579f, 0.3779644730092272f};
            sc = invsq[l] * ((rem == 0) ? 1.0f : 1.4142135623730951f);
        }
#pragma unroll
        for (int sp = 0; sp < NSP; ++sp) {
            int col;
            if (f < NPAIR)             col = NSP + NSP * NRAD + sp * NPAIR + f;
            else if (f < NPAIR + NRAD) col = NSP + sp * NRAD + (f - NPAIR);
            else                       col = sp;
            out[s * NCOLS + col] = sc * facc[k][sp];
        }
    }
}

extern "C" void kernel_launch(void* const* d_in, const int* in_sizes, int n_in,
                              void* d_out, int out_size) {
    const float* comp    = (const float*)d_in[0];
    const float* radial  = (const float*)d_in[1];
    const float* sph0    = (const float*)d_in[2];
    const float* sph1    = (const float*)d_in[3];
    const float* sph2    = (const float*)d_in[4];
    const float* sph3    = (const float*)d_in[5];
    const int*   sidx    = (const int*)d_in[6];
    const int*   species = (const int*)d_in[7];
    float*       out     = (float*)d_out;

    int n_atoms = in_sizes[0];
    int S       = out_size / NCOLS;
    if (S > SMAX) S = SMAX;

    cudaFuncSetAttribute(le_ace_kernel,
                         cudaFuncAttributeMaxDynamicSharedMemorySize, SM_TOTAL);

    setup_kernel<<<S, NTHREADS>>>(sidx, species, n_atoms);
    dim3 grid(S, FSPLIT);
    le_ace_kernel<<<grid, NTHREADS, SM_TOTAL>>>(comp, radial, sph0, sph1, sph2,
                                                sph3, out, n_atoms);
}

// round 16
// speedup vs baseline: 1.6959x; 1.6959x over previous
#include <cuda_runtime.h>
#include <cstdint>

namespace {
constexpr int NTSETUP = 256;
constexpr int NTHREADS = 512;          // one CTA per structure
constexpr int ST     = 33;             // smem coeff row stride (floats): conflict-free
constexpr int TILE   = 32;
constexpr int RST    = 64;             // radial tile row stride (floats)
constexpr int NCOEF  = 316;            // 32*1 + 24*3 + 20*5 + 16*7
constexpr int NPAIR  = 1174;           // 528 + 300 + 210 + 136
constexpr int NRAD   = 64;
constexpr int NSP    = 4;
constexpr int NFEAT  = NPAIR + NRAD + 1;   // 1239
constexpr int HSLOTS = 3;              // 3*512 = 1536 >= 1239
constexpr int SMAX   = 256;
constexpr int NCOLS  = NSP * NFEAT;    // 4956
constexpr int SM_TILE  = NCOEF * ST;               // floats
constexpr int SM_RAD   = TILE * RST;               // floats
constexpr int SM_TOTAL = (SM_TILE + SM_RAD + TILE) * 4;   // 50032 bytes
}

__device__ int g_run[SMAX * 5];        // run starts sp=0..3, then end (unpadded)
__device__ int g_order[1 << 16];       // atom idx sorted by (structure, species)

__device__ __forceinline__ void cpa4(uint32_t dst, const void* src, int sz) {
    asm volatile("cp.async.ca.shared.global [%0], [%1], 4, %2;"
                 :: "r"(dst), "l"(src), "r"(sz));
}
__device__ __forceinline__ void cpa16(uint32_t dst, const void* src, int sz) {
    asm volatile("cp.async.ca.shared.global [%0], [%1], 16, %2;"
                 :: "r"(dst), "l"(src), "r"(sz));
}
__device__ __forceinline__ void cpa_commit_wait() {
    asm volatile("cp.async.commit_group;" ::: "memory");
    asm volatile("cp.async.wait_group 0;" ::: "memory");
}

// One block per structure: binary-search bounds, then deterministic species sort
// (warp-major, lane-minor rank). Two passes: count, then scatter.
__global__ void setup_kernel(const int* __restrict__ sidx,
                             const int* __restrict__ species, int n_atoms) {
    const int s    = blockIdx.x;
    const int tid  = threadIdx.x;
    const int lane = tid & 31;
    const int wid  = tid >> 5;
    __shared__ int cnt[NSP], off[NSP], wcnt[8][NSP];

    int lo = 0, hi = n_atoms;
    while (lo < hi) { int mid = (lo + hi) >> 1; if (sidx[mid] < s) lo = mid + 1; else hi = mid; }
    const int a0 = lo;
    lo = a0; hi = n_atoms;
    while (lo < hi) { int mid = (lo + hi) >> 1; if (sidx[mid] < s + 1) lo = mid + 1; else hi = mid; }
    const int a1 = lo;

    if (tid < NSP) cnt[tid] = 0;
    __syncthreads();
    for (int chunk = a0; chunk < a1; chunk += NTSETUP) {
        const int n  = min(NTSETUP, a1 - chunk);
        const int sp = (tid < n) ? species[chunk + tid] : -1;
        const unsigned m = __match_any_sync(0xFFFFFFFFu, sp);
        if (sp >= 0 && (m & ((1u << lane) - 1u)) == 0)
            atomicAdd(&cnt[sp], __popc(m));
    }
    __syncthreads();
    if (tid == 0) {
        int p = a0;
#pragma unroll
        for (int q = 0; q < NSP; ++q) { g_run[s * 5 + q] = p; off[q] = p; p += cnt[q]; }
        g_run[s * 5 + 4] = p;
    }
    __syncthreads();
    for (int chunk = a0; chunk < a1; chunk += NTSETUP) {
        const int n  = min(NTSETUP, a1 - chunk);
        const int sp = (tid < n) ? species[chunk + tid] : -1;
        const unsigned m = __match_any_sync(0xFFFFFFFFu, sp);
        const int rank_w = __popc(m & ((1u << lane) - 1u));
        if (lane < NSP) wcnt[wid][lane] = 0;
        __syncthreads();
        if (sp >= 0 && rank_w == 0) wcnt[wid][sp] = __popc(m);
        __syncthreads();
        if (sp >= 0) {
            int pre = 0;
            for (int w = 0; w < wid; ++w) pre += wcnt[w][sp];
            g_order[off[sp] + pre + rank_w] = chunk + tid;
        }
        __syncthreads();
        if (tid < NSP) {
            int tot = 0;
#pragma unroll
            for (int w = 0; w < 8; ++w) tot += wcnt[w][tid];
            off[tid] += tot;
        }
        __syncthreads();
    }
}

// Pair invariant over [t0,t1): sum_j (-1)^j b1[j]*b2[D-1-j]
template<int D>
__device__ __forceinline__ float run_pairs(const float* __restrict__ b1,
                                           const float* __restrict__ b2,
                                           int t0, int t1) {
    float acc = 0.f;
#pragma unroll 2
    for (int t = t0; t < t1; ++t) {
        float v = b1[t] * b2[(D - 1) * ST + t];
#pragma unroll
        for (int j = 1; j < D; ++j) {
            float x = b1[j * ST + t] * b2[(D - 1 - j) * ST + t];
            v = (j & 1) ? (v - x) : (v + x);
        }
        acc += v;
    }
    return acc;
}

__global__ __launch_bounds__(NTHREADS, 2)
void le_ace_kernel(const float* __restrict__ comp,
                   const float* __restrict__ radial,
                   const float* __restrict__ sph0,
                   const float* __restrict__ sph1,
                   const float* __restrict__ sph2,
                   const float* __restrict__ sph3,
                   float* __restrict__ out,
                   int n_atoms) {
    extern __shared__ __align__(16) float smem[];
    float* tileS = smem;                    // [NCOEF * ST]
    float* radT  = smem + SM_TILE;          // [TILE * RST]
    float* compT = radT + SM_RAD;           // [TILE]

    const int tid  = threadIdx.x;
    const int lane = tid & 31;
    const int wid  = tid >> 5;              // 0..15
    const int s    = blockIdx.x;

    const uint32_t sb_tile = (uint32_t)__cvta_generic_to_shared(tileS);
    const uint32_t sb_rad  = (uint32_t)__cvta_generic_to_shared(radT);
    const uint32_t sb_cmp  = (uint32_t)__cvta_generic_to_shared(compT);

    // ---- per-thread feature-slot metadata ----
    // sdv: 1/3/5/7 = pair D; 0 = radial (sc1 = col); -1 = comp; -2 = inactive
    int   sc1[HSLOTS], sc2[HSLOTS], sdv[HSLOTS];
    float facc[HSLOTS][NSP];
#pragma unroll
    for (int k = 0; k < HSLOTS; ++k) {
        int f = k * NTHREADS + tid;
        sc1[k] = 0; sc2[k] = 0; sdv[k] = -2;
#pragma unroll
        for (int sp = 0; sp < NSP; ++sp) facc[k][sp] = 0.f;
        if (f < NFEAT) {
            if (f < NPAIR) {
                int l, q, base, coff;
                if (f < 528)       { l = 0; q = 32; base = 0;    coff = 0;   }
                else if (f < 828)  { l = 1; q = 24; base = 528;  coff = 32;  }
                else if (f < 1038) { l = 2; q = 20; base = 828;  coff = 104; }
                else               { l = 3; q = 16; base = 1038; coff = 204; }
                int rem = f - base, i1 = 0;
                while (rem >= q - i1) { rem -= q - i1; ++i1; }   // triangular inversion
                int i2 = i1 + rem;
                int d  = 2 * l + 1;
                sc1[k] = (coff + i1 * d) * ST;
                sc2[k] = (coff + i2 * d) * ST;
                sdv[k] = d;
            } else if (f < NPAIR + NRAD) {
                sdv[k] = 0; sc1[k] = f - NPAIR;
            } else {
                sdv[k] = -1;
            }
        }
    }

    int run[5];
#pragma unroll
    for (int r = 0; r < 5; ++r) run[r] = g_run[s * 5 + r];
    const int a0 = run[0];
    const int a1 = run[4];

    for (int base = a0; base < a1; base += TILE) {
        const int nt = min(TILE, a1 - base);
        __syncthreads();                     // previous tile fully consumed

        // ---- async staging: coeff rows, 16 warps x ~20 rows each ----
        const int  oL  = (base + lane < a1) ? g_order[base + lane] : -1;
        const int  oLc = max(oL, 0);
        const int  szL = (oL >= 0) ? 4 : 0;
        for (int c = wid; c < NCOEF; c += 16) {
            const float* p; int r;
            if (c < 32)       { p = sph0; r = c;       }
            else if (c < 104) { p = sph1; r = c - 32;  }
            else if (c < 204) { p = sph2; r = c - 104; }
            else              { p = sph3; r = c - 204; }
            cpa4(sb_tile + ((c * ST + lane) << 2), p + (long)r * n_atoms + oLc, szL);
        }
        // ---- radial tile: 32 atoms x 64 floats, one 16B chunk per thread ----
        {
            const int ta = tid >> 4;
            const int ch = tid & 15;
            const int o  = (base + ta < a1) ? g_order[base + ta] : -1;
            cpa16(sb_rad + (ta * RST + ch * 4) * 4,
                  radial + (long)max(o, 0) * NRAD + ch * 4, (o >= 0) ? 16 : 0);
        }
        // ---- comp tile ----
        if (tid < TILE)
            cpa4(sb_cmp + (tid << 2), comp + oLc, szL);
        cpa_commit_wait();
        __syncthreads();

        // ---- species bounds hoisted (shared by the 3 slots) ----
        int t0s[NSP], t1s[NSP];
#pragma unroll
        for (int sp = 0; sp < NSP; ++sp) {
            t0s[sp] = max(run[sp] - base, 0);
            t1s[sp] = min(run[sp + 1] - base, nt);
        }

        // ---- accumulate ----
#pragma unroll
        for (int k = 0; k < HSLOTS; ++k) {
            const int d = sdv[k];
            if (d > 0) {
                const float* b1 = tileS + sc1[k];
                const float* b2 = tileS + sc2[k];
#pragma unroll
                for (int sp = 0; sp < NSP; ++sp) {
                    const int t0 = t0s[sp], t1 = t1s[sp];
                    if (t0 >= t1) continue;
                    float v;
                    switch (d) {
                        case 1:  v = run_pairs<1>(b1, b2, t0, t1); break;
                        case 3:  v = run_pairs<3>(b1, b2, t0, t1); break;
                        case 5:  v = run_pairs<5>(b1, b2, t0, t1); break;
                        default: v = run_pairs<7>(b1, b2, t0, t1); break;
                    }
                    facc[k][sp] += v;
                }
            } else if (d == 0) {
                const int j = sc1[k];
#pragma unroll
                for (int sp = 0; sp < NSP; ++sp) {
                    float acc = 0.f;
                    for (int t = t0s[sp]; t < t1s[sp]; ++t)
                        acc += radT[t * RST + j];
                    facc[k][sp] += acc;
                }
            } else if (d == -1) {
#pragma unroll
                for (int sp = 0; sp < NSP; ++sp) {
                    float acc = 0.f;
                    for (int t = t0s[sp]; t < t1s[sp]; ++t)
                        acc += compT[t];
                    facc[k][sp] += acc;
                }
            }
        }
    }

    // ---- write: scale recomputed here (keeps it out of hot-loop registers) ----
#pragma unroll
    for (int k = 0; k < HSLOTS; ++k) {
        int f = k * NTHREADS + tid;
        if (f >= NFEAT) continue;
        float sc = 1.f;
        if (f < NPAIR) {
            int l, q, base;
            if (f < 528)       { l = 0; q = 32; base = 0;    }
            else if (f < 828)  { l = 1; q = 24; base = 528;  }
            else if (f < 1038) { l = 2; q = 20; base = 828;  }
            else               { l = 3; q = 16; base = 1038; }
            int rem = f - base, i1 = 0;
            while (rem >= q - i1) { rem -= q - i1; ++i1; }
            const float invsq[4] = {1.0f, 0.5773502691896258f,
                                    0.4472135954999579f, 0.3779644730092272f};
            sc = invsq[l] * ((rem == 0) ? 1.0f : 1.4142135623730951f);
        }
#pragma unroll
        for (int sp = 0; sp < NSP; ++sp) {
            int col;
            if (f < NPAIR)             col = NSP + NSP * NRAD + sp * NPAIR + f;
            else if (f < NPAIR + NRAD) col = NSP + sp * NRAD + (f - NPAIR);
            else                       col = sp;
            out[s * NCOLS + col] = sc * facc[k][sp];
        }
    }
}

extern "C" void kernel_launch(void* const* d_in, const int* in_sizes, int n_in,
                              void* d_out, int out_size) {
    const float* comp    = (const float*)d_in[0];
    const float* radial  = (const float*)d_in[1];
    const float* sph0    = (const float*)d_in[2];
    const float* sph1    = (const float*)d_in[3];
    const float* sph2    = (const float*)d_in[4];
    const float* sph3    = (const float*)d_in[5];
    const int*   sidx    = (const int*)d_in[6];
    const int*   species = (const int*)d_in[7];
    float*       out     = (float*)d_out;

    int n_atoms = in_sizes[0];
    int S       = out_size / NCOLS;
    if (S > SMAX) S = SMAX;

    cudaFuncSetAttribute(le_ace_kernel,
                         cudaFuncAttributeMaxDynamicSharedMemorySize, SM_TOTAL);

    setup_kernel<<<S, NTSETUP>>>(sidx, species, n_atoms);
    le_ace_kernel<<<S, NTHREADS, SM_TOTAL>>>(comp, radial, sph0, sph1, sph2,
                                             sph3, out, n_atoms);
}

// round 17
// speedup vs baseline: 1.7716x; 1.0447x over previous
#include <cuda_runtime.h>
#include <cstdint>

namespace {
constexpr int NTHREADS = 512;          // one CTA per structure
constexpr int TILE   = 64;
constexpr int ST     = 65;             // smem coeff row stride (floats): odd -> conflict-free
constexpr int RST    = 64;             // radial tile row stride (floats)
constexpr int NCOEF  = 316;            // 32*1 + 24*3 + 20*5 + 16*7
constexpr int NPAIR  = 1174;           // 528 + 300 + 210 + 136
constexpr int NRAD   = 64;
constexpr int NSP    = 4;
constexpr int NFEAT  = NPAIR + NRAD + 1;   // 1239
constexpr int HSLOTS = 3;              // 3*512 = 1536 >= 1239
constexpr int SMAX   = 256;
constexpr int NCOLS  = NSP * NFEAT;    // 4956
constexpr int CAP    = 2048;           // max atoms per structure (avg 64; huge margin)
constexpr int SM_TILE  = NCOEF * ST;               // floats = 20540
constexpr int SM_RAD   = TILE * RST;               // floats = 4096
constexpr int SM_FLOATS = SM_TILE + SM_RAD + TILE; // 24700
constexpr int SM_TOTAL  = SM_FLOATS * 4 + CAP * 4; // 107'— 106992 bytes
}

__device__ __forceinline__ void cpa4(uint32_t dst, const void* src, int sz) {
    asm volatile("cp.async.ca.shared.global [%0], [%1], 4, %2;"
                 :: "r"(dst), "l"(src), "r"(sz));
}
__device__ __forceinline__ void cpa16(uint32_t dst, const void* src, int sz) {
    asm volatile("cp.async.ca.shared.global [%0], [%1], 16, %2;"
                 :: "r"(dst), "l"(src), "r"(sz));
}
__device__ __forceinline__ void cpa_commit_wait() {
    asm volatile("cp.async.commit_group;" ::: "memory");
    asm volatile("cp.async.wait_group 0;" ::: "memory");
}

// Pair invariant over [t0,t1): sum_j (-1)^j b1[j]*b2[D-1-j]
template<int D>
__device__ __forceinline__ float run_pairs(const float* __restrict__ b1,
                                           const float* __restrict__ b2,
                                           int t0, int t1) {
    float acc = 0.f;
#pragma unroll 2
    for (int t = t0; t < t1; ++t) {
        float v = b1[t] * b2[(D - 1) * ST + t];
#pragma unroll
        for (int j = 1; j < D; ++j) {
            float x = b1[j * ST + t] * b2[(D - 1 - j) * ST + t];
            v = (j & 1) ? (v - x) : (v + x);
        }
        acc += v;
    }
    return acc;
}

__global__ __launch_bounds__(NTHREADS, 2)
void le_ace_kernel(const float* __restrict__ comp,
                   const float* __restrict__ radial,
                   const float* __restrict__ sph0,
                   const float* __restrict__ sph1,
                   const float* __restrict__ sph2,
                   const float* __restrict__ sph3,
                   const int* __restrict__ sidx,
                   const int* __restrict__ species,
                   float* __restrict__ out,
                   int n_atoms) {
    extern __shared__ __align__(16) float smem[];
    float* tileS = smem;                       // [NCOEF * ST]
    float* radT  = smem + SM_TILE;             // [TILE * RST]
    float* compT = radT + SM_RAD;              // [TILE]
    int*   sord  = (int*)(smem + SM_FLOATS);   // [CAP] atoms sorted by species

    __shared__ int cnt[NSP], off[NSP], runsh[5], wcnt[16][NSP];

    const int tid  = threadIdx.x;
    const int lane = tid & 31;
    const int wid  = tid >> 5;              // 0..15
    const int s    = blockIdx.x;

    const uint32_t sb_tile = (uint32_t)__cvta_generic_to_shared(tileS);
    const uint32_t sb_rad  = (uint32_t)__cvta_generic_to_shared(radT);
    const uint32_t sb_cmp  = (uint32_t)__cvta_generic_to_shared(compT);

    // ---- structure bounds: binary search in sorted structure_index ----
    int lo = 0, hi = n_atoms;
    while (lo < hi) { int mid = (lo + hi) >> 1; if (sidx[mid] < s) lo = mid + 1; else hi = mid; }
    const int a0 = lo;
    hi = n_atoms;
    while (lo < hi) { int mid = (lo + hi) >> 1; if (sidx[mid] < s + 1) lo = mid + 1; else hi = mid; }
    const int a1 = lo;
    const int natoms = min(a1 - a0, CAP);

    // ---- in-CTA deterministic species sort (warp-major, lane-minor rank) ----
    if (tid < NSP) cnt[tid] = 0;
    __syncthreads();
    for (int chunk = 0; chunk < natoms; chunk += NTHREADS) {
        const int n  = min(NTHREADS, natoms - chunk);
        const int sp = (tid < n) ? species[a0 + chunk + tid] : -1;
        const unsigned m = __match_any_sync(0xFFFFFFFFu, sp);
        if (sp >= 0 && (m & ((1u << lane) - 1u)) == 0)
            atomicAdd(&cnt[sp], __popc(m));
    }
    __syncthreads();
    if (tid == 0) {
        int p = 0;
#pragma unroll
        for (int q = 0; q < NSP; ++q) { runsh[q] = p; off[q] = p; p += cnt[q]; }
        runsh[4] = p;
    }
    __syncthreads();
    for (int chunk = 0; chunk < natoms; chunk += NTHREADS) {
        const int n  = min(NTHREADS, natoms - chunk);
        const int sp = (tid < n) ? species[a0 + chunk + tid] : -1;
        const unsigned m = __match_any_sync(0xFFFFFFFFu, sp);
        const int rank_w = __popc(m & ((1u << lane) - 1u));
        if (lane < NSP) wcnt[wid][lane] = 0;
        __syncthreads();
        if (sp >= 0 && rank_w == 0) wcnt[wid][sp] = __popc(m);
        __syncthreads();
        if (sp >= 0) {
            int pre = 0;
            for (int w = 0; w < wid; ++w) pre += wcnt[w][sp];
            sord[off[sp] + pre + rank_w] = a0 + chunk + tid;
        }
        __syncthreads();
        if (tid < NSP) {
            int tot = 0;
#pragma unroll
            for (int w = 0; w < 16; ++w) tot += wcnt[w][tid];
            off[tid] += tot;
        }
        __syncthreads();
    }

    // ---- per-thread feature-slot metadata ----
    // sdv: 1/3/5/7 = pair D; 0 = radial (sc1 = col); -1 = comp; -2 = inactive
    int   sc1[HSLOTS], sc2[HSLOTS], sdv[HSLOTS];
    float facc[HSLOTS][NSP];
#pragma unroll
    for (int k = 0; k < HSLOTS; ++k) {
        int f = k * NTHREADS + tid;
        sc1[k] = 0; sc2[k] = 0; sdv[k] = -2;
#pragma unroll
        for (int sp = 0; sp < NSP; ++sp) facc[k][sp] = 0.f;
        if (f < NFEAT) {
            if (f < NPAIR) {
                int l, q, base, coff;
                if (f < 528)       { l = 0; q = 32; base = 0;    coff = 0;   }
                else if (f < 828)  { l = 1; q = 24; base = 528;  coff = 32;  }
                else if (f < 1038) { l = 2; q = 20; base = 828;  coff = 104; }
                else               { l = 3; q = 16; base = 1038; coff = 204; }
                int rem = f - base, i1 = 0;
                while (rem >= q - i1) { rem -= q - i1; ++i1; }   // triangular inversion
                int i2 = i1 + rem;
                int d  = 2 * l + 1;
                sc1[k] = (coff + i1 * d) * ST;
                sc2[k] = (coff + i2 * d) * ST;
                sdv[k] = d;
            } else if (f < NPAIR + NRAD) {
                sdv[k] = 0; sc1[k] = f - NPAIR;
            } else {
                sdv[k] = -1;
            }
        }
    }

    int run[5];
#pragma unroll
    for (int r = 0; r < 5; ++r) run[r] = runsh[r];

    for (int base = 0; base < natoms; base += TILE) {
        const int nt = min(TILE, natoms - base);
        if (base) __syncthreads();           // previous tile fully consumed

        // ---- async staging: coeff rows; each row needs 64 lanes (2 cp/lane) ----
        const int  o0  = (base + lane < natoms) ? sord[base + lane] : -1;
        const int  o1  = (base + 32 + lane < natoms) ? sord[base + 32 + lane] : -1;
        const int  o0c = max(o0, 0), o1c = max(o1, 0);
        const int  sz0 = (o0 >= 0) ? 4 : 0, sz1 = (o1 >= 0) ? 4 : 0;
        for (int c = wid; c < NCOEF; c += 16) {
            const float* p; int r;
            if (c < 32)       { p = sph0; r = c;       }
            else if (c < 104) { p = sph1; r = c - 32;  }
            else if (c < 204) { p = sph2; r = c - 104; }
            else              { p = sph3; r = c - 204; }
            const float* row = p + (long)r * n_atoms;
            cpa4(sb_tile + ((c * ST + lane) << 2),      row + o0c, sz0);
            cpa4(sb_tile + ((c * ST + 32 + lane) << 2), row + o1c, sz1);
        }
        // ---- radial tile: 64 atoms x 64 floats, 16B chunks ----
#pragma unroll
        for (int i = 0; i < 2; ++i) {
            const int idx = tid + NTHREADS * i;   // 0..1023
            const int ta  = idx >> 4;
            const int ch  = idx & 15;
            const int o   = (base + ta < natoms) ? sord[base + ta] : -1;
            cpa16(sb_rad + (ta * RST + ch * 4) * 4,
                  radial + (long)max(o, 0) * NRAD + ch * 4, (o >= 0) ? 16 : 0);
        }
        // ---- comp tile ----
        if (tid < TILE) {
            const int o = (base + tid < natoms) ? sord[base + tid] : -1;
            cpa4(sb_cmp + (tid << 2), comp + max(o, 0), (o >= 0) ? 4 : 0);
        }
        cpa_commit_wait();
        __syncthreads();

        // ---- species bounds hoisted (shared by the 3 slots) ----
        int t0s[NSP], t1s[NSP];
#pragma unroll
        for (int sp = 0; sp < NSP; ++sp) {
            t0s[sp] = max(run[sp] - base, 0);
            t1s[sp] = min(run[sp + 1] - base, nt);
        }

        // ---- accumulate ----
#pragma unroll
        for (int k = 0; k < HSLOTS; ++k) {
            const int d = sdv[k];
            if (d > 0) {
                const float* b1 = tileS + sc1[k];
                const float* b2 = tileS + sc2[k];
#pragma unroll
                for (int sp = 0; sp < NSP; ++sp) {
                    const int t0 = t0s[sp], t1 = t1s[sp];
                    if (t0 >= t1) continue;
                    float v;
                    switch (d) {
                        case 1:  v = run_pairs<1>(b1, b2, t0, t1); break;
                        case 3:  v = run_pairs<3>(b1, b2, t0, t1); break;
                        case 5:  v = run_pairs<5>(b1, b2, t0, t1); break;
                        default: v = run_pairs<7>(b1, b2, t0, t1); break;
                    }
                    facc[k][sp] += v;
                }
            } else if (d == 0) {
                const int j = sc1[k];
#pragma unroll
                for (int sp = 0; sp < NSP; ++sp) {
                    float acc = 0.f;
                    for (int t = t0s[sp]; t < t1s[sp]; ++t)
                        acc += radT[t * RST + j];
                    facc[k][sp] += acc;
                }
            } else if (d == -1) {
#pragma unroll
                for (int sp = 0; sp < NSP; ++sp) {
                    float acc = 0.f;
                    for (int t = t0s[sp]; t < t1s[sp]; ++t)
                        acc += compT[t];
                    facc[k][sp] += acc;
                }
            }
        }
    }

    // ---- write: scale recomputed here (keeps it out of hot-loop registers) ----
#pragma unroll
    for (int k = 0; k < HSLOTS; ++k) {
        int f = k * NTHREADS + tid;
        if (f >= NFEAT) continue;
        float sc = 1.f;
        if (f < NPAIR) {
            int l, q, base;
            if (f < 528)       { l = 0; q = 32; base = 0;    }
            else if (f < 828)  { l = 1; q = 24; base = 528;  }
            else if (f < 1038) { l = 2; q = 20; base = 828;  }
            else               { l = 3; q = 16; base = 1038; }
            int rem = f - base, i1 = 0;
            while (rem >= q - i1) { rem -= q - i1; ++i1; }
            const float invsq[4] = {1.0f, 0.5773502691896258f,
                                    0.4472135954999579f, 0.3779644730092272f};
            sc = invsq[l] * ((rem == 0) ? 1.0f : 1.4142135623730951f);
        }
#pragma unroll
        for (int sp = 0; sp < NSP; ++sp) {
            int col;
            if (f < NPAIR)             col = NSP + NSP * NRAD + sp * NPAIR + f;
            else if (f < NPAIR + NRAD) col = NSP + sp * NRAD + (f - NPAIR);
            else                       col = sp;
            out[s * NCOLS + col] = sc * facc[k][sp];
        }
    }
}

extern "C" void kernel_launch(void* const* d_in, const int* in_sizes, int n_in,
                              void* d_out, int out_size) {
    const float* comp    = (const float*)d_in[0];
    const float* radial  = (const float*)d_in[1];
    const float* sph0    = (const float*)d_in[2];
    const float* sph1    = (const float*)d_in[3];
    const float* sph2    = (const float*)d_in[4];
    const float* sph3    = (const float*)d_in[5];
    const int*   sidx    = (const int*)d_in[6];
    const int*   species = (const int*)d_in[7];
    float*       out     = (float*)d_out;

    int n_atoms = in_sizes[0];
    int S       = out_size / NCOLS;
    if (S > SMAX) S = SMAX;

    cudaFuncSetAttribute(le_ace_kernel,
                         cudaFuncAttributeMaxDynamicSharedMemorySize, SM_TOTAL);

    le_ace_kernel<<<S, NTHREADS, SM_TOTAL>>>(comp, radial, sph0, sph1, sph2,
                                             sph3, sidx, species, out, n_atoms);
}